// round 1
// baseline (speedup 1.0000x reference)
#include <cuda_runtime.h>
#include <math.h>

// Cosine-sim attention, B=256, nH=8, N=256, d=64, fp32.
// One CTA per (b,h). SMEM: q_s 64KB | k_s 64KB (xor-swizzled float4) | v_s 64KB | p_s 32KB.
// 8 warps x 32 q-rows each; gemm1 register-blocked 8 rows x 8 k-cols per lane.

#define SMEM_FLOATS 57344
#define SMEM_BYTES  (SMEM_FLOATS * 4)
#define LOG100F 4.605170185988092f

__global__ void __launch_bounds__(256, 1)
attn_cos_kernel(const float* __restrict__ q,
                const float* __restrict__ k,
                const float* __restrict__ v,
                const float* __restrict__ ls,
                const float* __restrict__ bias,
                float* __restrict__ out)
{
    extern __shared__ float smem[];
    float* q_s = smem;            // [256][64] row-major
    float* k_s = smem + 16384;    // [256][64], float4-granule xor swizzle
    float* v_s = smem + 32768;    // [256][64] row-major
    float* p_s = smem + 49152;    // 8 warps * 4 rows * 256

    const int bh  = blockIdx.x;       // 0..2047
    const int b   = bh >> 3;
    const int h   = bh & 7;
    const int tid = threadIdx.x;
    const int w   = tid >> 5;
    const int j   = tid & 31;

    const float* __restrict__ qg = q + (size_t)bh * 16384;
    const float* __restrict__ kg = k + (size_t)bh * 16384;
    const float* __restrict__ vg = v + (size_t)bh * 16384;
    const float* __restrict__ bg = bias + (size_t)h * 65536;
    float* __restrict__ og = out + (size_t)b * 131072 + (size_t)h * 64;

    const float scale = __expf(fminf(ls[h], LOG100F));

    // ---- load V (plain row-major copy) ----
    {
        const float4* v4g = (const float4*)vg;
        float4* v4s = (float4*)v_s;
        #pragma unroll
        for (int it = 0; it < 16; ++it)
            v4s[tid + it * 256] = v4g[tid + it * 256];
    }

    // ---- load + L2-normalize Q and K; warp w owns rows [w*32, w*32+32) ----
    for (int rr = 0; rr < 32; ++rr) {
        const int n = w * 32 + rr;
        float a0 = qg[n * 64 + j];
        float a1 = qg[n * 64 + 32 + j];
        float c0 = kg[n * 64 + j];
        float c1 = kg[n * 64 + 32 + j];
        float sq = a0 * a0 + a1 * a1;
        float sk = c0 * c0 + c1 * c1;
        #pragma unroll
        for (int o = 16; o > 0; o >>= 1) {
            sq += __shfl_xor_sync(0xffffffffu, sq, o);
            sk += __shfl_xor_sync(0xffffffffu, sk, o);
        }
        const float iq = 1.0f / fmaxf(sqrtf(sq), 1e-12f);
        const float ik = 1.0f / fmaxf(sqrtf(sk), 1e-12f);
        q_s[n * 64 + j]      = a0 * iq;
        q_s[n * 64 + 32 + j] = a1 * iq;
        // swizzled K store: logical float4 L in row n lands at physical L^(n&7)
        const int swn = n & 7;
        k_s[n * 64 + (((j >> 2) ^ swn) << 2) + (j & 3)]        = c0 * ik;
        k_s[n * 64 + ((((j >> 2) + 8) ^ swn) << 2) + (j & 3)]  = c1 * ik;
    }
    __syncthreads();

    const float4* k4 = (const float4*)k_s;
    const float4* q4 = (const float4*)q_s;
    const float2* v2 = (const float2*)v_s;
    float* pw = p_s + w * 1024;
    const int sw = j & 7;   // == (32*jj + j) & 7 for all jj

    for (int g = 0; g < 4; ++g) {
        const int n0 = w * 32 + g * 8;

        // ---- GEMM1: scores for 8 q-rows; lane j covers m = jj*32 + j ----
        float s[8][8];
        #pragma unroll
        for (int r = 0; r < 8; ++r)
            #pragma unroll
            for (int jj = 0; jj < 8; ++jj) s[r][jj] = 0.0f;

        #pragma unroll 1
        for (int i4 = 0; i4 < 16; ++i4) {
            float4 kv[8];
            #pragma unroll
            for (int jj = 0; jj < 8; ++jj)
                kv[jj] = k4[(jj * 32 + j) * 16 + (i4 ^ sw)];   // conflict-free via swizzle
            #pragma unroll
            for (int r = 0; r < 8; ++r) {
                const float4 qv = q4[(n0 + r) * 16 + i4];       // broadcast
                #pragma unroll
                for (int jj = 0; jj < 8; ++jj) {
                    s[r][jj] = fmaf(qv.x, kv[jj].x, s[r][jj]);
                    s[r][jj] = fmaf(qv.y, kv[jj].y, s[r][jj]);
                    s[r][jj] = fmaf(qv.z, kv[jj].z, s[r][jj]);
                    s[r][jj] = fmaf(qv.w, kv[jj].w, s[r][jj]);
                }
            }
        }

        // ---- scale + bias (coalesced) + softmax (warp shuffle) ----
        float linv[8];
        #pragma unroll
        for (int r = 0; r < 8; ++r) {
            const int n = n0 + r;
            float mx = -1e30f;
            #pragma unroll
            for (int jj = 0; jj < 8; ++jj) {
                float t = fmaf(s[r][jj], scale, bg[n * 256 + jj * 32 + j]);
                s[r][jj] = t;
                mx = fmaxf(mx, t);
            }
            #pragma unroll
            for (int o = 16; o > 0; o >>= 1)
                mx = fmaxf(mx, __shfl_xor_sync(0xffffffffu, mx, o));
            float sum = 0.0f;
            #pragma unroll
            for (int jj = 0; jj < 8; ++jj) {
                float p = __expf(s[r][jj] - mx);
                s[r][jj] = p;
                sum += p;
            }
            #pragma unroll
            for (int o = 16; o > 0; o >>= 1)
                sum += __shfl_xor_sync(0xffffffffu, sum, o);
            linv[r] = 1.0f / sum;
        }

        // ---- PV: stage P to SMEM, then broadcast-P x lane<->d V ----
        #pragma unroll
        for (int sb = 0; sb < 2; ++sb) {
            #pragma unroll
            for (int rr = 0; rr < 4; ++rr)
                #pragma unroll
                for (int jj = 0; jj < 8; ++jj)
                    pw[rr * 256 + jj * 32 + j] = s[sb * 4 + rr][jj];
            __syncwarp();

            float acc[4][2];
            #pragma unroll
            for (int rr = 0; rr < 4; ++rr) { acc[rr][0] = 0.0f; acc[rr][1] = 0.0f; }

            const float4* p4 = (const float4*)pw;
            #pragma unroll 2
            for (int m4 = 0; m4 < 64; ++m4) {
                const float2 vv0 = v2[(m4 * 4 + 0) * 32 + j];
                const float2 vv1 = v2[(m4 * 4 + 1) * 32 + j];
                const float2 vv2 = v2[(m4 * 4 + 2) * 32 + j];
                const float2 vv3 = v2[(m4 * 4 + 3) * 32 + j];
                #pragma unroll
                for (int rr = 0; rr < 4; ++rr) {
                    const float4 pp = p4[rr * 64 + m4];   // broadcast
                    acc[rr][0] = fmaf(pp.x, vv0.x, acc[rr][0]);
                    acc[rr][1] = fmaf(pp.x, vv0.y, acc[rr][1]);
                    acc[rr][0] = fmaf(pp.y, vv1.x, acc[rr][0]);
                    acc[rr][1] = fmaf(pp.y, vv1.y, acc[rr][1]);
                    acc[rr][0] = fmaf(pp.z, vv2.x, acc[rr][0]);
                    acc[rr][1] = fmaf(pp.z, vv2.y, acc[rr][1]);
                    acc[rr][0] = fmaf(pp.w, vv3.x, acc[rr][0]);
                    acc[rr][1] = fmaf(pp.w, vv3.y, acc[rr][1]);
                }
            }

            #pragma unroll
            for (int rr = 0; rr < 4; ++rr) {
                const int n = n0 + sb * 4 + rr;
                float2 o2;
                o2.x = acc[rr][0] * linv[sb * 4 + rr];
                o2.y = acc[rr][1] * linv[sb * 4 + rr];
                // out[b, n*512 + h*64 + d], lane covers d = 2j, 2j+1
                *(float2*)(og + (size_t)n * 512 + 2 * j) = o2;
            }
            __syncwarp();
        }
    }
}

extern "C" void kernel_launch(void* const* d_in, const int* in_sizes, int n_in,
                              void* d_out, int out_size)
{
    const float* q    = (const float*)d_in[0];
    const float* k    = (const float*)d_in[1];
    const float* v    = (const float*)d_in[2];
    const float* ls   = (const float*)d_in[3];
    const float* bias = (const float*)d_in[4];
    float* out = (float*)d_out;
    (void)in_sizes; (void)n_in; (void)out_size;

    cudaFuncSetAttribute(attn_cos_kernel,
                         cudaFuncAttributeMaxDynamicSharedMemorySize, SMEM_BYTES);
    attn_cos_kernel<<<2048, 256, SMEM_BYTES>>>(q, k, v, ls, bias, out);
}

// round 3
// speedup vs baseline: 1.4954x; 1.4954x over previous
#include <cuda_runtime.h>
#include <cuda_bf16.h>
#include <cstdint>
#include <math.h>

#define LOG100F 4.605170185988092f

// SMEM word offsets (uint32 units)
#define QHI 0
#define QLO 9216
#define KHI 18432
#define KLO 27648
#define VHI 36864   // 64 rows * 132 words
#define VLO 45312
#define SMEM_WORDS 53760
#define SMEM_BYTES (SMEM_WORDS * 4)   // 215040

static __device__ __forceinline__ void mma_bf16(float* d, const uint32_t* a,
                                                uint32_t b0, uint32_t b1) {
    asm volatile(
        "mma.sync.aligned.m16n8k16.row.col.f32.bf16.bf16.f32 "
        "{%0,%1,%2,%3}, {%4,%5,%6,%7}, {%8,%9}, {%0,%1,%2,%3};"
        : "+f"(d[0]), "+f"(d[1]), "+f"(d[2]), "+f"(d[3])
        : "r"(a[0]), "r"(a[1]), "r"(a[2]), "r"(a[3]), "r"(b0), "r"(b1));
}

static __device__ __forceinline__ void packsplit(float x, float y,
                                                 uint32_t& hi, uint32_t& lo) {
    __nv_bfloat16 hx = __float2bfloat16(x), hy = __float2bfloat16(y);
    float rx = x - __bfloat162float(hx);
    float ry = y - __bfloat162float(hy);
    __nv_bfloat16 lx = __float2bfloat16(rx), ly = __float2bfloat16(ry);
    hi = ((uint32_t)__bfloat16_as_ushort(hy) << 16) | __bfloat16_as_ushort(hx);
    lo = ((uint32_t)__bfloat16_as_ushort(ly) << 16) | __bfloat16_as_ushort(lx);
}

__global__ void __launch_bounds__(256, 1)
attn_mma_kernel(const float* __restrict__ q, const float* __restrict__ k,
                const float* __restrict__ v, const float* __restrict__ ls,
                const float* __restrict__ bias, float* __restrict__ out)
{
    extern __shared__ uint32_t sm[];
    const int tid = threadIdx.x;
    const int w = tid >> 5, j = tid & 31;
    const int g = j >> 2, tg = j & 3;
    const int bh = blockIdx.x, b = bh >> 3, h = bh & 7;

    const float* __restrict__ qg = q + (size_t)bh * 16384;
    const float* __restrict__ kg = k + (size_t)bh * 16384;
    const float* __restrict__ vg = v + (size_t)bh * 16384;
    const float* __restrict__ bg = bias + (size_t)h * 65536;
    float* __restrict__ og = out + (size_t)b * 131072 + (size_t)h * 64;
    const float scale = __expf(fminf(ls[h], LOG100F));

    // ---- phase 0: normalize q,k; pack bf16 hi/lo into SMEM ----
    #pragma unroll 1
    for (int rr = 0; rr < 32; ++rr) {
        const int n = w * 32 + rr;
        const float2 qv = *(const float2*)(qg + (size_t)n * 64 + 2 * j);
        const float2 kv = *(const float2*)(kg + (size_t)n * 64 + 2 * j);
        float sq = qv.x * qv.x + qv.y * qv.y;
        float sk = kv.x * kv.x + kv.y * kv.y;
        #pragma unroll
        for (int o = 16; o > 0; o >>= 1) {
            sq += __shfl_xor_sync(0xffffffffu, sq, o);
            sk += __shfl_xor_sync(0xffffffffu, sk, o);
        }
        const float iq = 1.0f / fmaxf(sqrtf(sq), 1e-12f);
        const float ik = 1.0f / fmaxf(sqrtf(sk), 1e-12f);
        uint32_t hi, lo;
        packsplit(qv.x * iq, qv.y * iq, hi, lo);
        sm[QHI + n * 36 + j] = hi; sm[QLO + n * 36 + j] = lo;
        packsplit(kv.x * ik, kv.y * ik, hi, lo);
        sm[KHI + n * 36 + j] = hi; sm[KLO + n * 36 + j] = lo;
    }
    // ---- V: transposed, kv-pair-packed: vt[d][m2] = (V[2m2][d], V[2m2+1][d]) ----
    #pragma unroll 1
    for (int rr = 0; rr < 16; ++rr) {
        const int m2 = w * 16 + rr;
        const float* r0 = vg + (size_t)(2 * m2) * 64;
        const float* r1 = r0 + 64;
        float a0 = r0[j], a1 = r0[j + 32];
        float b0 = r1[j], b1 = r1[j + 32];
        uint32_t hi, lo;
        packsplit(a0, b0, hi, lo);
        sm[VHI + j * 132 + m2] = hi; sm[VLO + j * 132 + m2] = lo;
        packsplit(a1, b1, hi, lo);
        sm[VHI + (j + 32) * 132 + m2] = hi; sm[VLO + (j + 32) * 132 + m2] = lo;
    }
    __syncthreads();

    // ---- main loop: warp owns rows [m0, m0+32); online softmax over 8 chunks ----
    const int m0 = w * 32;
    float o[2][8][4];
    #pragma unroll
    for (int mt = 0; mt < 2; ++mt)
        #pragma unroll
        for (int dt = 0; dt < 8; ++dt)
            #pragma unroll
            for (int e = 0; e < 4; ++e) o[mt][dt][e] = 0.0f;
    float rmax[4] = {-3.0e38f, -3.0e38f, -3.0e38f, -3.0e38f};
    float rsum[4] = {0.0f, 0.0f, 0.0f, 0.0f};

    #pragma unroll 1
    for (int c = 0; c < 8; ++c) {
        // GEMM1: S[32 rows][32 cols] = Qn . Kn^T, 3 split terms
        float s[2][4][4];
        #pragma unroll
        for (int mt = 0; mt < 2; ++mt)
            #pragma unroll
            for (int nt = 0; nt < 4; ++nt)
                #pragma unroll
                for (int e = 0; e < 4; ++e) s[mt][nt][e] = 0.0f;

        #pragma unroll
        for (int ks = 0; ks < 4; ++ks) {
            uint32_t ahi[2][4], alo[2][4];
            #pragma unroll
            for (int mt = 0; mt < 2; ++mt) {
                const int r0 = (m0 + 16 * mt + g) * 36 + 8 * ks + tg;
                const int r1 = r0 + 8 * 36;
                ahi[mt][0] = sm[QHI + r0]; ahi[mt][1] = sm[QHI + r1];
                ahi[mt][2] = sm[QHI + r0 + 4]; ahi[mt][3] = sm[QHI + r1 + 4];
                alo[mt][0] = sm[QLO + r0]; alo[mt][1] = sm[QLO + r1];
                alo[mt][2] = sm[QLO + r0 + 4]; alo[mt][3] = sm[QLO + r1 + 4];
            }
            #pragma unroll
            for (int nt = 0; nt < 4; ++nt) {
                const int kn = (32 * c + 8 * nt + g) * 36 + 8 * ks + tg;
                const uint32_t bh0 = sm[KHI + kn], bh1 = sm[KHI + kn + 4];
                const uint32_t bl0 = sm[KLO + kn], bl1 = sm[KLO + kn + 4];
                #pragma unroll
                for (int mt = 0; mt < 2; ++mt) {
                    mma_bf16(s[mt][nt], ahi[mt], bh0, bh1);
                    mma_bf16(s[mt][nt], ahi[mt], bl0, bl1);
                    mma_bf16(s[mt][nt], alo[mt], bh0, bh1);
                }
            }
        }

        // logits = s*scale + bias; chunk row-max
        float cmax[4] = {-3.0e38f, -3.0e38f, -3.0e38f, -3.0e38f};
        #pragma unroll
        for (int mt = 0; mt < 2; ++mt)
            #pragma unroll
            for (int nt = 0; nt < 4; ++nt) {
                const int rl = m0 + 16 * mt + g;
                const int col = 32 * c + 8 * nt + 2 * tg;
                const float2 bL = __ldg((const float2*)(bg + (size_t)rl * 256 + col));
                const float2 bH = __ldg((const float2*)(bg + (size_t)(rl + 8) * 256 + col));
                s[mt][nt][0] = fmaf(s[mt][nt][0], scale, bL.x);
                s[mt][nt][1] = fmaf(s[mt][nt][1], scale, bL.y);
                s[mt][nt][2] = fmaf(s[mt][nt][2], scale, bH.x);
                s[mt][nt][3] = fmaf(s[mt][nt][3], scale, bH.y);
                cmax[2 * mt]     = fmaxf(cmax[2 * mt],     fmaxf(s[mt][nt][0], s[mt][nt][1]));
                cmax[2 * mt + 1] = fmaxf(cmax[2 * mt + 1], fmaxf(s[mt][nt][2], s[mt][nt][3]));
            }
        #pragma unroll
        for (int ri = 0; ri < 4; ++ri) {
            cmax[ri] = fmaxf(cmax[ri], __shfl_xor_sync(0xffffffffu, cmax[ri], 1));
            cmax[ri] = fmaxf(cmax[ri], __shfl_xor_sync(0xffffffffu, cmax[ri], 2));
        }

        // online rescale
        float fac[4];
        #pragma unroll
        for (int ri = 0; ri < 4; ++ri) {
            const float nm = fmaxf(rmax[ri], cmax[ri]);
            fac[ri] = __expf(rmax[ri] - nm);
            rmax[ri] = nm;
            rsum[ri] *= fac[ri];
        }
        #pragma unroll
        for (int mt = 0; mt < 2; ++mt)
            #pragma unroll
            for (int dt = 0; dt < 8; ++dt) {
                o[mt][dt][0] *= fac[2 * mt];     o[mt][dt][1] *= fac[2 * mt];
                o[mt][dt][2] *= fac[2 * mt + 1]; o[mt][dt][3] *= fac[2 * mt + 1];
            }

        // exp + chunk row-sum
        float cs[4] = {0.0f, 0.0f, 0.0f, 0.0f};
        #pragma unroll
        for (int mt = 0; mt < 2; ++mt)
            #pragma unroll
            for (int nt = 0; nt < 4; ++nt) {
                s[mt][nt][0] = __expf(s[mt][nt][0] - rmax[2 * mt]);
                s[mt][nt][1] = __expf(s[mt][nt][1] - rmax[2 * mt]);
                s[mt][nt][2] = __expf(s[mt][nt][2] - rmax[2 * mt + 1]);
                s[mt][nt][3] = __expf(s[mt][nt][3] - rmax[2 * mt + 1]);
                cs[2 * mt]     += s[mt][nt][0] + s[mt][nt][1];
                cs[2 * mt + 1] += s[mt][nt][2] + s[mt][nt][3];
            }
        #pragma unroll
        for (int ri = 0; ri < 4; ++ri) {
            cs[ri] += __shfl_xor_sync(0xffffffffu, cs[ri], 1);
            cs[ri] += __shfl_xor_sync(0xffffffffu, cs[ri], 2);
            rsum[ri] += cs[ri];
        }

        // pack P into A-fragments (in-register D->A layout identity)
        uint32_t phi[2][2][4], plo[2][2][4];
        #pragma unroll
        for (int mt = 0; mt < 2; ++mt)
            #pragma unroll
            for (int a = 0; a < 2; ++a) {
                packsplit(s[mt][2 * a][0],     s[mt][2 * a][1],     phi[mt][a][0], plo[mt][a][0]);
                packsplit(s[mt][2 * a][2],     s[mt][2 * a][3],     phi[mt][a][1], plo[mt][a][1]);
                packsplit(s[mt][2 * a + 1][0], s[mt][2 * a + 1][1], phi[mt][a][2], plo[mt][a][2]);
                packsplit(s[mt][2 * a + 1][2], s[mt][2 * a + 1][3], phi[mt][a][3], plo[mt][a][3]);
            }

        // GEMM2: O += P . V  (V pre-transposed/pair-packed)
        #pragma unroll
        for (int a = 0; a < 2; ++a)
            #pragma unroll
            for (int dt = 0; dt < 8; ++dt) {
                const int vb = (8 * dt + g) * 132 + 16 * c + 8 * a + tg;
                const uint32_t bh0 = sm[VHI + vb], bh1 = sm[VHI + vb + 4];
                const uint32_t bl0 = sm[VLO + vb], bl1 = sm[VLO + vb + 4];
                #pragma unroll
                for (int mt = 0; mt < 2; ++mt) {
                    mma_bf16(o[mt][dt], phi[mt][a], bh0, bh1);
                    mma_bf16(o[mt][dt], phi[mt][a], bl0, bl1);
                    mma_bf16(o[mt][dt], plo[mt][a], bh0, bh1);
                }
            }
    }

    // ---- epilogue: normalize, store transposed (b, n*512 + h*64 + d) ----
    #pragma unroll
    for (int mt = 0; mt < 2; ++mt) {
        const float inv0 = 1.0f / rsum[2 * mt];
        const float inv1 = 1.0f / rsum[2 * mt + 1];
        const int rl = m0 + 16 * mt + g;
        #pragma unroll
        for (int dt = 0; dt < 8; ++dt) {
            float2 v0, v1;
            v0.x = o[mt][dt][0] * inv0; v0.y = o[mt][dt][1] * inv0;
            v1.x = o[mt][dt][2] * inv1; v1.y = o[mt][dt][3] * inv1;
            *(float2*)(og + (size_t)rl * 512 + 8 * dt + 2 * tg) = v0;
            *(float2*)(og + (size_t)(rl + 8) * 512 + 8 * dt + 2 * tg) = v1;
        }
    }
}

extern "C" void kernel_launch(void* const* d_in, const int* in_sizes, int n_in,
                              void* d_out, int out_size)
{
    const float* q    = (const float*)d_in[0];
    const float* k    = (const float*)d_in[1];
    const float* v    = (const float*)d_in[2];
    const float* ls   = (const float*)d_in[3];
    const float* bias = (const float*)d_in[4];
    float* out = (float*)d_out;
    (void)in_sizes; (void)n_in; (void)out_size;

    cudaFuncSetAttribute(attn_mma_kernel,
                         cudaFuncAttributeMaxDynamicSharedMemorySize, SMEM_BYTES);
    attn_mma_kernel<<<2048, 256, SMEM_BYTES>>>(q, k, v, ls, bias, out);
}

// round 4
// speedup vs baseline: 2.0866x; 1.3953x over previous
#include <cuda_runtime.h>
#include <cuda_bf16.h>
#include <cstdint>
#include <math.h>

#define LOG100F 4.605170185988092f

// SMEM word offsets (uint32 units). hi/lo interleaved: word pair (hi,lo).
#define QW 0            // 256 rows * 72 words  (32 k-pairs * 2 + 8 pad)
#define KW 18432        // 256 rows * 72
#define VW 36864        // V^T: 64 rows * 264 words (128 m2-pairs * 2 + 8 pad)
#define SMEM_WORDS 53760
#define SMEM_BYTES (SMEM_WORDS * 4)   // 215040

static __device__ __forceinline__ void mma_bf16(float* d, const uint32_t* a,
                                                uint32_t b0, uint32_t b1) {
    asm volatile(
        "mma.sync.aligned.m16n8k16.row.col.f32.bf16.bf16.f32 "
        "{%0,%1,%2,%3}, {%4,%5,%6,%7}, {%8,%9}, {%0,%1,%2,%3};"
        : "+f"(d[0]), "+f"(d[1]), "+f"(d[2]), "+f"(d[3])
        : "r"(a[0]), "r"(a[1]), "r"(a[2]), "r"(a[3]), "r"(b0), "r"(b1));
}

static __device__ __forceinline__ void packsplit(float x, float y,
                                                 uint32_t& hi, uint32_t& lo) {
    __nv_bfloat16 hx = __float2bfloat16(x), hy = __float2bfloat16(y);
    float rx = x - __bfloat162float(hx);
    float ry = y - __bfloat162float(hy);
    __nv_bfloat16 lx = __float2bfloat16(rx), ly = __float2bfloat16(ry);
    hi = ((uint32_t)__bfloat16_as_ushort(hy) << 16) | __bfloat16_as_ushort(hx);
    lo = ((uint32_t)__bfloat16_as_ushort(ly) << 16) | __bfloat16_as_ushort(lx);
}

__global__ void __launch_bounds__(512, 1)
attn_mma16_kernel(const float* __restrict__ q, const float* __restrict__ k,
                  const float* __restrict__ v, const float* __restrict__ ls,
                  const float* __restrict__ bias, float* __restrict__ out)
{
    extern __shared__ uint32_t sm[];
    const int tid = threadIdx.x;
    const int w = tid >> 5, j = tid & 31;
    const int g = j >> 2, tg = j & 3;
    const int bh = blockIdx.x, b = bh >> 3, h = bh & 7;

    const float* __restrict__ qg = q + (size_t)bh * 16384;
    const float* __restrict__ kg = k + (size_t)bh * 16384;
    const float* __restrict__ vg = v + (size_t)bh * 16384;
    const float* __restrict__ bg = bias + (size_t)h * 65536;
    float* __restrict__ og = out + (size_t)b * 131072 + (size_t)h * 64;
    const float scale = __expf(fminf(ls[h], LOG100F));

    // ---- phase 0: normalize q,k; pack bf16 (hi,lo) word-pairs into SMEM ----
    #pragma unroll 1
    for (int rr = 0; rr < 16; ++rr) {
        const int n = w * 16 + rr;
        const float2 qv = *(const float2*)(qg + (size_t)n * 64 + 2 * j);
        const float2 kv = *(const float2*)(kg + (size_t)n * 64 + 2 * j);
        float sq = qv.x * qv.x + qv.y * qv.y;
        float sk = kv.x * kv.x + kv.y * kv.y;
        #pragma unroll
        for (int o = 16; o > 0; o >>= 1) {
            sq += __shfl_xor_sync(0xffffffffu, sq, o);
            sk += __shfl_xor_sync(0xffffffffu, sk, o);
        }
        const float iq = 1.0f / fmaxf(sqrtf(sq), 1e-12f);
        const float ik = 1.0f / fmaxf(sqrtf(sk), 1e-12f);
        uint32_t hi, lo;
        packsplit(qv.x * iq, qv.y * iq, hi, lo);
        *(uint2*)&sm[QW + n * 72 + 2 * j] = make_uint2(hi, lo);
        packsplit(kv.x * ik, kv.y * ik, hi, lo);
        *(uint2*)&sm[KW + n * 72 + 2 * j] = make_uint2(hi, lo);
    }
    // V^T pair-packed: row d, pair p=(V[2p][d],V[2p+1][d]); lane covers d=j, j+32
    #pragma unroll 1
    for (int rr = 0; rr < 8; ++rr) {
        const int p = w * 8 + rr;
        const float* r0 = vg + (size_t)(2 * p) * 64;
        const float* r1 = r0 + 64;
        uint32_t hi, lo;
        packsplit(r0[j], r1[j], hi, lo);
        *(uint2*)&sm[VW + j * 264 + 2 * p] = make_uint2(hi, lo);
        packsplit(r0[j + 32], r1[j + 32], hi, lo);
        *(uint2*)&sm[VW + (j + 32) * 264 + 2 * p] = make_uint2(hi, lo);
    }
    __syncthreads();

    // ---- main loop: warp owns rows [m0, m0+16); online softmax, 8 kv-chunks ----
    const int m0 = w * 16;
    const int rl = m0 + g;
    float o[8][4];
    #pragma unroll
    for (int dt = 0; dt < 8; ++dt)
        #pragma unroll
        for (int e = 0; e < 4; ++e) o[dt][e] = 0.0f;
    float rmax[2] = {-3.0e38f, -3.0e38f};
    float rsum[2] = {0.0f, 0.0f};

    const uint32_t* qrow0 = &sm[QW + rl * 72];
    const uint32_t* qrow1 = qrow0 + 8 * 72;

    #pragma unroll 1
    for (int c = 0; c < 8; ++c) {
        // GEMM1: S[16 rows][32 cols], 3 split terms
        float s[4][4];
        #pragma unroll
        for (int nt = 0; nt < 4; ++nt)
            #pragma unroll
            for (int e = 0; e < 4; ++e) s[nt][e] = 0.0f;

        #pragma unroll
        for (int ks = 0; ks < 4; ++ks) {
            const int wbase = (8 * ks + tg) * 2;
            const uint2 a00 = *(const uint2*)(qrow0 + wbase);
            const uint2 a10 = *(const uint2*)(qrow1 + wbase);
            const uint2 a01 = *(const uint2*)(qrow0 + wbase + 8);
            const uint2 a11 = *(const uint2*)(qrow1 + wbase + 8);
            const uint32_t ahi[4] = {a00.x, a10.x, a01.x, a11.x};
            const uint32_t alo[4] = {a00.y, a10.y, a01.y, a11.y};
            #pragma unroll
            for (int nt = 0; nt < 4; ++nt) {
                const uint32_t* krow = &sm[KW + (32 * c + 8 * nt + g) * 72];
                const uint2 b0 = *(const uint2*)(krow + wbase);
                const uint2 b1 = *(const uint2*)(krow + wbase + 8);
                mma_bf16(s[nt], ahi, b0.x, b1.x);
                mma_bf16(s[nt], ahi, b0.y, b1.y);
                mma_bf16(s[nt], alo, b0.x, b1.x);
            }
        }

        // logits = s*scale + bias; chunk row-max
        float cmax[2] = {-3.0e38f, -3.0e38f};
        #pragma unroll
        for (int nt = 0; nt < 4; ++nt) {
            const int col = 32 * c + 8 * nt + 2 * tg;
            const float2 bL = __ldg((const float2*)(bg + (size_t)rl * 256 + col));
            const float2 bH = __ldg((const float2*)(bg + (size_t)(rl + 8) * 256 + col));
            s[nt][0] = fmaf(s[nt][0], scale, bL.x);
            s[nt][1] = fmaf(s[nt][1], scale, bL.y);
            s[nt][2] = fmaf(s[nt][2], scale, bH.x);
            s[nt][3] = fmaf(s[nt][3], scale, bH.y);
            cmax[0] = fmaxf(cmax[0], fmaxf(s[nt][0], s[nt][1]));
            cmax[1] = fmaxf(cmax[1], fmaxf(s[nt][2], s[nt][3]));
        }
        #pragma unroll
        for (int ri = 0; ri < 2; ++ri) {
            cmax[ri] = fmaxf(cmax[ri], __shfl_xor_sync(0xffffffffu, cmax[ri], 1));
            cmax[ri] = fmaxf(cmax[ri], __shfl_xor_sync(0xffffffffu, cmax[ri], 2));
        }

        // online rescale
        float fac[2];
        #pragma unroll
        for (int ri = 0; ri < 2; ++ri) {
            const float nm = fmaxf(rmax[ri], cmax[ri]);
            fac[ri] = __expf(rmax[ri] - nm);
            rmax[ri] = nm;
            rsum[ri] *= fac[ri];
        }
        #pragma unroll
        for (int dt = 0; dt < 8; ++dt) {
            o[dt][0] *= fac[0]; o[dt][1] *= fac[0];
            o[dt][2] *= fac[1]; o[dt][3] *= fac[1];
        }

        // exp + chunk row-sum
        float cs[2] = {0.0f, 0.0f};
        #pragma unroll
        for (int nt = 0; nt < 4; ++nt) {
            s[nt][0] = __expf(s[nt][0] - rmax[0]);
            s[nt][1] = __expf(s[nt][1] - rmax[0]);
            s[nt][2] = __expf(s[nt][2] - rmax[1]);
            s[nt][3] = __expf(s[nt][3] - rmax[1]);
            cs[0] += s[nt][0] + s[nt][1];
            cs[1] += s[nt][2] + s[nt][3];
        }
        #pragma unroll
        for (int ri = 0; ri < 2; ++ri) {
            cs[ri] += __shfl_xor_sync(0xffffffffu, cs[ri], 1);
            cs[ri] += __shfl_xor_sync(0xffffffffu, cs[ri], 2);
            rsum[ri] += cs[ri];
        }

        // pack P into A-fragments (in-register D->A layout identity)
        uint32_t phi[2][4], plo[2][4];
        #pragma unroll
        for (int a = 0; a < 2; ++a) {
            packsplit(s[2 * a][0],     s[2 * a][1],     phi[a][0], plo[a][0]);
            packsplit(s[2 * a][2],     s[2 * a][3],     phi[a][1], plo[a][1]);
            packsplit(s[2 * a + 1][0], s[2 * a + 1][1], phi[a][2], plo[a][2]);
            packsplit(s[2 * a + 1][2], s[2 * a + 1][3], phi[a][3], plo[a][3]);
        }

        // GEMM2: O += P . V^T
        #pragma unroll
        for (int a = 0; a < 2; ++a)
            #pragma unroll
            for (int dt = 0; dt < 8; ++dt) {
                const uint32_t* vrow = &sm[VW + (8 * dt + g) * 264 + (16 * c + 8 * a + tg) * 2];
                const uint2 v0 = *(const uint2*)(vrow);
                const uint2 v1 = *(const uint2*)(vrow + 8);
                mma_bf16(o[dt], phi[a], v0.x, v1.x);
                mma_bf16(o[dt], phi[a], v0.y, v1.y);
                mma_bf16(o[dt], plo[a], v0.x, v1.x);
            }
    }

    // ---- epilogue: normalize, store transposed (b, n*512 + h*64 + d) ----
    const float inv0 = 1.0f / rsum[0];
    const float inv1 = 1.0f / rsum[1];
    #pragma unroll
    for (int dt = 0; dt < 8; ++dt) {
        float2 v0, v1;
        v0.x = o[dt][0] * inv0; v0.y = o[dt][1] * inv0;
        v1.x = o[dt][2] * inv1; v1.y = o[dt][3] * inv1;
        *(float2*)(og + (size_t)rl * 512 + 8 * dt + 2 * tg) = v0;
        *(float2*)(og + (size_t)(rl + 8) * 512 + 8 * dt + 2 * tg) = v1;
    }
}

extern "C" void kernel_launch(void* const* d_in, const int* in_sizes, int n_in,
                              void* d_out, int out_size)
{
    const float* q    = (const float*)d_in[0];
    const float* k    = (const float*)d_in[1];
    const float* v    = (const float*)d_in[2];
    const float* ls   = (const float*)d_in[3];
    const float* bias = (const float*)d_in[4];
    float* out = (float*)d_out;
    (void)in_sizes; (void)n_in; (void)out_size;

    cudaFuncSetAttribute(attn_mma16_kernel,
                         cudaFuncAttributeMaxDynamicSharedMemorySize, SMEM_BYTES);
    attn_mma16_kernel<<<2048, 512, SMEM_BYTES>>>(q, k, v, ls, bias, out);
}